// round 1
// baseline (speedup 1.0000x reference)
#include <cuda_runtime.h>
#include <cuda_bf16.h>
#include <cfloat>
#include <cstddef>

// Problem dims
#define BATCH   2
#define SLEN    2048
#define HID     2048
#define NHEADS  16
#define HDIM    128
#define H3      6144            // 3*HID
#define MROWS   4096            // BATCH*SLEN

// ---------------- scratch (static device arrays; no allocations) -------------
__device__ float g_proj[(size_t)MROWS * H3];   // QKV projection output  (~100MB)
__device__ float g_ctx [(size_t)MROWS * HID];  // attention context      (~33MB)

// ======================= GEMM: C[M,N] = A[M,K] * B[N,K]^T ====================
// A row-major [M,K], B row-major [N,K]. 128x128 tile, BK=16, 256 threads,
// 8x8 per-thread (rows ty*8.., cols tx*4.. and 64+tx*4..).
#define GBM 128
#define GBN 128
#define GBK 16

__global__ __launch_bounds__(256, 2)
void gemm_nt(const float* __restrict__ A, const float* __restrict__ B,
             float* __restrict__ C, int M, int N, int K)
{
    __shared__ float As[GBK][GBM + 4];
    __shared__ float Bs[GBK][GBN + 4];

    const int bx = blockIdx.x;       // N tile
    const int by = blockIdx.y;       // M tile
    const int tid = threadIdx.x;
    const int tx = tid & 15;         // 0..15
    const int ty = tid >> 4;         // 0..15

    const float* Ag = A + (size_t)by * GBM * K;
    const float* Bg = B + (size_t)bx * GBN * K;

    float acc[8][8];
#pragma unroll
    for (int i = 0; i < 8; i++)
#pragma unroll
        for (int j = 0; j < 8; j++) acc[i][j] = 0.f;

    for (int k0 = 0; k0 < K; k0 += GBK) {
        // Load tiles: 128 rows x 16 cols = 512 float4 per matrix, 2 per thread
#pragma unroll
        for (int t = 0; t < 2; t++) {
            int idx = tid + t * 256;         // 0..511
            int r   = idx >> 2;              // 0..127
            int c4  = idx & 3;               // float4 index 0..3
            float4 a = *(const float4*)(Ag + (size_t)r * K + k0 + c4 * 4);
            As[c4*4+0][r] = a.x; As[c4*4+1][r] = a.y;
            As[c4*4+2][r] = a.z; As[c4*4+3][r] = a.w;
            float4 bb = *(const float4*)(Bg + (size_t)r * K + k0 + c4 * 4);
            Bs[c4*4+0][r] = bb.x; Bs[c4*4+1][r] = bb.y;
            Bs[c4*4+2][r] = bb.z; Bs[c4*4+3][r] = bb.w;
        }
        __syncthreads();

#pragma unroll
        for (int k = 0; k < GBK; k++) {
            float4 a0 = *(const float4*)(&As[k][ty * 8]);
            float4 a1 = *(const float4*)(&As[k][ty * 8 + 4]);
            float4 b0 = *(const float4*)(&Bs[k][tx * 4]);
            float4 b1 = *(const float4*)(&Bs[k][tx * 4 + 64]);
            float ar[8] = {a0.x,a0.y,a0.z,a0.w,a1.x,a1.y,a1.z,a1.w};
            float br[8] = {b0.x,b0.y,b0.z,b0.w,b1.x,b1.y,b1.z,b1.w};
#pragma unroll
            for (int i = 0; i < 8; i++)
#pragma unroll
                for (int j = 0; j < 8; j++)
                    acc[i][j] += ar[i] * br[j];
        }
        __syncthreads();
    }

    float* Cb = C + (size_t)(by * GBM + ty * 8) * N + bx * GBN;
#pragma unroll
    for (int i = 0; i < 8; i++) {
        *(float4*)(Cb + (size_t)i * N + tx * 4)      = make_float4(acc[i][0], acc[i][1], acc[i][2], acc[i][3]);
        *(float4*)(Cb + (size_t)i * N + 64 + tx * 4) = make_float4(acc[i][4], acc[i][5], acc[i][6], acc[i][7]);
    }
}

// ======================= Flash attention (causal) ============================
// Per block: one (batch, head, 64-row q tile). 256 threads.
// Thread mapping (S): rows r0..r0+3 (r0=(tid>>4)*4), cols cg+16*j (cg=tid&15).
// Output accumulation: rows r0..r0+3, dims {d0..d0+3, d0+64..d0+67}, d0=cg*4.
#define FBM 64
#define FBN 64
#define QP  132
#define KP  132
#define VP  132
#define PP  65
#define SOFTMAX_SCALE 0.08838834764831845f   // 1/sqrt(128)

__global__ __launch_bounds__(256, 1)
void flash_kernel(const float* __restrict__ proj, float* __restrict__ ctx)
{
    extern __shared__ float sm[];
    float* Qs = sm;                   // FBM x QP
    float* Ks = Qs + FBM * QP;        // FBN x KP
    float* Vs = Ks + FBN * KP;        // FBN x VP
    float* Ps = Vs + FBN * VP;        // FBM x PP

    const int q0  = blockIdx.x * FBM;
    const int h   = blockIdx.y;
    const int b   = blockIdx.z;
    const int tid = threadIdx.x;
    const int rg  = tid >> 4;         // 0..15
    const int cg  = tid & 15;         // 0..15
    const int r0  = rg * 4;
    const int d0  = cg * 4;

    // row base in proj for this (b, row): (b*SLEN + row)*H3 + h*HDIM + sel*HID
    // --- Load Q tile (sel = 0) ---
    for (int t = tid; t < FBM * 32; t += 256) {
        int r = t >> 5, kk = t & 31;
        const float* src = proj + (size_t)(b * SLEN + q0 + r) * H3 + h * HDIM;
        *(float4*)(Qs + r * QP + kk * 4) = *(const float4*)(src + kk * 4);
    }
    __syncthreads();

    float m[4], l[4], o[4][8];
#pragma unroll
    for (int i = 0; i < 4; i++) {
        m[i] = -FLT_MAX; l[i] = 0.f;
#pragma unroll
        for (int j = 0; j < 8; j++) o[i][j] = 0.f;
    }

    for (int k0 = 0; k0 <= q0; k0 += FBN) {
        // --- Load K (sel=1) and V (sel=2) tiles ---
        for (int t = tid; t < FBN * 32; t += 256) {
            int c = t >> 5, kk = t & 31;
            const float* base = proj + (size_t)(b * SLEN + k0 + c) * H3 + h * HDIM;
            *(float4*)(Ks + c * KP + kk * 4) = *(const float4*)(base + HID  + kk * 4);
            *(float4*)(Vs + c * VP + kk * 4) = *(const float4*)(base + 2*HID + kk * 4);
        }
        __syncthreads();

        // --- S = Q K^T * scale ---
        float acc[4][4];
#pragma unroll
        for (int i = 0; i < 4; i++)
#pragma unroll
            for (int j = 0; j < 4; j++) acc[i][j] = 0.f;

#pragma unroll 4
        for (int kk = 0; kk < 32; kk++) {
            float4 q4[4];
#pragma unroll
            for (int i = 0; i < 4; i++)
                q4[i] = *(const float4*)(Qs + (r0 + i) * QP + kk * 4);
#pragma unroll
            for (int j = 0; j < 4; j++) {
                float4 k4 = *(const float4*)(Ks + (cg + 16 * j) * KP + kk * 4);
#pragma unroll
                for (int i = 0; i < 4; i++) {
                    acc[i][j] += q4[i].x * k4.x + q4[i].y * k4.y
                               + q4[i].z * k4.z + q4[i].w * k4.w;
                }
            }
        }

        const bool diag = (k0 == q0);
#pragma unroll
        for (int i = 0; i < 4; i++)
#pragma unroll
            for (int j = 0; j < 4; j++) {
                acc[i][j] *= SOFTMAX_SCALE;
                if (diag) {
                    int qi = q0 + r0 + i;
                    int kj = k0 + cg + 16 * j;
                    if (kj > qi) acc[i][j] = -FLT_MAX;
                }
            }

        // --- row max over the 16 lanes of this row group ---
        float p[4][4];
        float rsum[4];
#pragma unroll
        for (int i = 0; i < 4; i++) {
            float tm = acc[i][0];
#pragma unroll
            for (int j = 1; j < 4; j++) tm = fmaxf(tm, acc[i][j]);
            tm = fmaxf(tm, __shfl_xor_sync(0xffffffffu, tm, 1));
            tm = fmaxf(tm, __shfl_xor_sync(0xffffffffu, tm, 2));
            tm = fmaxf(tm, __shfl_xor_sync(0xffffffffu, tm, 4));
            tm = fmaxf(tm, __shfl_xor_sync(0xffffffffu, tm, 8));
            float newm = fmaxf(m[i], tm);
            float alpha = __expf(m[i] - newm);
            m[i] = newm;
            float s = 0.f;
#pragma unroll
            for (int j = 0; j < 4; j++) {
                p[i][j] = __expf(acc[i][j] - newm);
                s += p[i][j];
            }
            s += __shfl_xor_sync(0xffffffffu, s, 1);
            s += __shfl_xor_sync(0xffffffffu, s, 2);
            s += __shfl_xor_sync(0xffffffffu, s, 4);
            s += __shfl_xor_sync(0xffffffffu, s, 8);
            rsum[i] = s;
            l[i] = l[i] * alpha + s;
#pragma unroll
            for (int j = 0; j < 8; j++) o[i][j] *= alpha;
        }
        (void)rsum;

        // --- stage P to smem ---
#pragma unroll
        for (int i = 0; i < 4; i++)
#pragma unroll
            for (int j = 0; j < 4; j++)
                Ps[(r0 + i) * PP + cg + 16 * j] = p[i][j];
        __syncthreads();

        // --- O += P @ V ---
#pragma unroll 2
        for (int c = 0; c < FBN; c++) {
            float pv[4];
#pragma unroll
            for (int i = 0; i < 4; i++) pv[i] = Ps[(r0 + i) * PP + c];
            float4 v0 = *(const float4*)(Vs + c * VP + d0);
            float4 v1 = *(const float4*)(Vs + c * VP + 64 + d0);
#pragma unroll
            for (int i = 0; i < 4; i++) {
                o[i][0] += pv[i] * v0.x; o[i][1] += pv[i] * v0.y;
                o[i][2] += pv[i] * v0.z; o[i][3] += pv[i] * v0.w;
                o[i][4] += pv[i] * v1.x; o[i][5] += pv[i] * v1.y;
                o[i][6] += pv[i] * v1.z; o[i][7] += pv[i] * v1.w;
            }
        }
        __syncthreads();   // before next tile overwrites Ks/Vs
    }

    // --- finalize: divide by l, write context ---
#pragma unroll
    for (int i = 0; i < 4; i++) {
        float inv = 1.f / l[i];
        float* dst = ctx + (size_t)(b * SLEN + q0 + r0 + i) * HID + h * HDIM;
        *(float4*)(dst + d0)      = make_float4(o[i][0]*inv, o[i][1]*inv, o[i][2]*inv, o[i][3]*inv);
        *(float4*)(dst + 64 + d0) = make_float4(o[i][4]*inv, o[i][5]*inv, o[i][6]*inv, o[i][7]*inv);
    }
}

// ============================ host entry =====================================
extern "C" void kernel_launch(void* const* d_in, const int* in_sizes, int n_in,
                              void* d_out, int out_size)
{
    const float* hidden = (const float*)d_in[0];
    // d_in[1] is the additive causal mask; we implement causality directly.
    const float* w_pack = (const float*)d_in[2];
    const float* w_o    = (const float*)d_in[3];
    float* out = (float*)d_out;

    float *proj, *ctx;
    cudaGetSymbolAddress((void**)&proj, g_proj);
    cudaGetSymbolAddress((void**)&ctx,  g_ctx);

    // 1) QKV projection: proj[4096, 6144] = hidden[4096,2048] @ w_pack[6144,2048]^T
    gemm_nt<<<dim3(H3 / GBN, MROWS / GBM), 256>>>(hidden, w_pack, proj, MROWS, H3, HID);

    // 2) causal flash attention per (qtile, head, batch)
    int smem_bytes = (FBM * QP + FBN * KP + FBN * VP + FBM * PP) * (int)sizeof(float);
    cudaFuncSetAttribute(flash_kernel, cudaFuncAttributeMaxDynamicSharedMemorySize, smem_bytes);
    flash_kernel<<<dim3(SLEN / FBM, NHEADS, BATCH), 256, smem_bytes>>>(proj, ctx);

    // 3) output projection: out[4096,2048] = ctx[4096,2048] @ w_o[2048,2048]^T
    gemm_nt<<<dim3(HID / GBN, MROWS / GBM), 256>>>(ctx, w_o, out, MROWS, HID, HID);
}

// round 3
// speedup vs baseline: 1.2463x; 1.2463x over previous
#include <cuda_runtime.h>
#include <cuda_bf16.h>
#include <cfloat>
#include <cstdint>
#include <cstddef>

// Problem dims
#define BATCH   2
#define SLEN    2048
#define HID     2048
#define NHEADS  16
#define HDIM    128
#define H3      6144
#define MROWS   4096

// ---------------- scratch (static device arrays; no allocations) -------------
__device__ float g_proj[(size_t)MROWS * H3];   // QKV projection output
__device__ float g_ctx [(size_t)MROWS * HID];  // attention context
// bf16 hi/lo split scratch (A reused for hidden then ctx; B for w_pack then w_o)
__device__ __nv_bfloat16 g_ah[(size_t)MROWS * HID];
__device__ __nv_bfloat16 g_al[(size_t)MROWS * HID];
__device__ __nv_bfloat16 g_bh[(size_t)H3 * HID];
__device__ __nv_bfloat16 g_bl[(size_t)H3 * HID];

// ===================== small PTX helpers =====================================
__device__ __forceinline__ uint32_t smem_u32(const void* p) {
    uint32_t a;
    asm("{ .reg .u64 t; cvta.to.shared.u64 t, %1; cvt.u32.u64 %0, t; }"
        : "=r"(a) : "l"(p));
    return a;
}
__device__ __forceinline__ void cp_async16(uint32_t saddr, const void* gaddr) {
    asm volatile("cp.async.cg.shared.global [%0], [%1], 16;"
                 :: "r"(saddr), "l"(gaddr) : "memory");
}
__device__ __forceinline__ void cp_commit() {
    asm volatile("cp.async.commit_group;" ::: "memory");
}
template <int N>
__device__ __forceinline__ void cp_wait() {
    asm volatile("cp.async.wait_group %0;" :: "n"(N) : "memory");
}
__device__ __forceinline__ void ldsm_x4(uint32_t* r, uint32_t addr) {
    asm volatile("ldmatrix.sync.aligned.m8n8.x4.shared.b16 {%0,%1,%2,%3}, [%4];"
                 : "=r"(r[0]), "=r"(r[1]), "=r"(r[2]), "=r"(r[3]) : "r"(addr));
}
__device__ __forceinline__ void mma16816(float* c, const uint32_t* a, const uint32_t* b) {
    asm volatile(
        "mma.sync.aligned.m16n8k16.row.col.f32.bf16.bf16.f32 "
        "{%0,%1,%2,%3}, {%4,%5,%6,%7}, {%8,%9}, {%0,%1,%2,%3};"
        : "+f"(c[0]), "+f"(c[1]), "+f"(c[2]), "+f"(c[3])
        : "r"(a[0]), "r"(a[1]), "r"(a[2]), "r"(a[3]), "r"(b[0]), "r"(b[1]));
}

// ================= fp32 -> bf16 hi/lo split (elementwise) ====================
__global__ __launch_bounds__(256)
void split_kernel(const float* __restrict__ src, __nv_bfloat16* __restrict__ hi,
                  __nv_bfloat16* __restrict__ lo, int n)
{
    int i4 = blockIdx.x * blockDim.x + threadIdx.x;   // index of float4
    if (i4 * 4 >= n) return;
    float4 v = *(const float4*)(src + i4 * 4);
    float x[4] = {v.x, v.y, v.z, v.w};
    __nv_bfloat16 h[4], l[4];
#pragma unroll
    for (int j = 0; j < 4; j++) {
        h[j] = __float2bfloat16_rn(x[j]);
        l[j] = __float2bfloat16_rn(x[j] - __bfloat162float(h[j]));
    }
    ushort4 hp, lp;
    hp.x = *(uint16_t*)&h[0]; hp.y = *(uint16_t*)&h[1];
    hp.z = *(uint16_t*)&h[2]; hp.w = *(uint16_t*)&h[3];
    lp.x = *(uint16_t*)&l[0]; lp.y = *(uint16_t*)&l[1];
    lp.z = *(uint16_t*)&l[2]; lp.w = *(uint16_t*)&l[3];
    *(ushort4*)(hi + i4 * 4) = hp;
    *(ushort4*)(lo + i4 * 4) = lp;
}

// ========== tensor-core GEMM: C[M,N] = A[M,K] * B[N,K]^T, fp32 out ==========
// A,B given pre-split as bf16 hi/lo. 3-product Markidis accumulate in fp32.
// BM=BN=128, BK=32, 256 threads, 8 warps in 4(M)x2(N); warp tile 32x64.
// smem per stage: Ahi|Alo|Bhi|Blo, each [kc(4)][row(128)][16B] = 8KB -> 32KB.
#define GBM 128
#define GBN 128
#define GBK 32
#define MAT_BYTES 8192
#define STAGE_BYTES 32768
#define GT_SMEM (2 * STAGE_BYTES)

__global__ __launch_bounds__(256, 1)
void gemm_bf16s(const __nv_bfloat16* __restrict__ Ah, const __nv_bfloat16* __restrict__ Al,
                const __nv_bfloat16* __restrict__ Bh, const __nv_bfloat16* __restrict__ Bl,
                float* __restrict__ C, int N, int K)
{
    extern __shared__ char sm[];
    const uint32_t sbase = smem_u32(sm);
    const int tid  = threadIdx.x;
    const int wid  = tid >> 5;
    const int lane = tid & 31;
    const int bx = blockIdx.x;    // N tile
    const int by = blockIdx.y;    // M tile
    const int wm = wid >> 1;      // 0..3
    const int wn = wid & 1;       // 0..1

    const __nv_bfloat16* gsrc[4] = {
        Ah + (size_t)by * GBM * K, Al + (size_t)by * GBM * K,
        Bh + (size_t)bx * GBN * K, Bl + (size_t)bx * GBN * K };

    // cp.async mapping: idx -> (mat, row, kc)
    // idx = i*256 + tid, mat = idx>>9, within = idx&511, row = within>>2, kc = within&3
    auto prefetch = [&](int c) {
        const int stage = c & 1;
        const uint32_t sst = sbase + stage * STAGE_BYTES;
        const int k0 = c * GBK;
#pragma unroll
        for (int i = 0; i < 8; i++) {
            int idx = i * 256 + tid;
            int mat = idx >> 9;
            int within = idx & 511;
            int row = within >> 2;
            int kc = within & 3;
            const __nv_bfloat16* g = gsrc[mat] + (size_t)row * K + k0 + kc * 8;
            uint32_t s = sst + mat * MAT_BYTES + kc * 2048 + row * 16;
            cp_async16(s, g);
        }
        cp_commit();
    };

    // ldmatrix per-lane address components
    const int subA = lane >> 3;
    const int rowoffA = (lane & 7) + (subA & 1) * 8;
    const int kcselA  = subA >> 1;
    const int rowoffB = (lane & 7) + ((lane >> 4) * 8);   // sub>>1
    const int kcselB  = (lane >> 3) & 1;                  // sub&1

    float acc[2][8][4];
#pragma unroll
    for (int mt = 0; mt < 2; mt++)
#pragma unroll
        for (int nt = 0; nt < 8; nt++)
#pragma unroll
            for (int q = 0; q < 4; q++) acc[mt][nt][q] = 0.f;

    const int KC = K / GBK;
    prefetch(0);

    for (int c = 0; c < KC; c++) {
        __syncthreads();                    // stage (c+1)&1 free of readers
        if (c + 1 < KC) { prefetch(c + 1); cp_wait<1>(); }
        else            { cp_wait<0>(); }
        __syncthreads();

        const uint32_t sst = sbase + (c & 1) * STAGE_BYTES;
        const uint32_t aBaseHi = sst + 0 * MAT_BYTES;
        const uint32_t aBaseLo = sst + 1 * MAT_BYTES;
        const uint32_t bBaseHi = sst + 2 * MAT_BYTES;
        const uint32_t bBaseLo = sst + 3 * MAT_BYTES;

#pragma unroll
        for (int ks = 0; ks < 2; ks++) {
            uint32_t ah[2][4], al[2][4], bh[4][4], bl[4][4];
#pragma unroll
            for (int mt = 0; mt < 2; mt++) {
                uint32_t roff = (uint32_t)((ks * 2 + kcselA) * 2048 +
                                           (wm * 32 + mt * 16 + rowoffA) * 16);
                ldsm_x4(ah[mt], aBaseHi + roff);
                ldsm_x4(al[mt], aBaseLo + roff);
            }
#pragma unroll
            for (int np = 0; np < 4; np++) {
                uint32_t roff = (uint32_t)((ks * 2 + kcselB) * 2048 +
                                           (wn * 64 + np * 16 + rowoffB) * 16);
                ldsm_x4(bh[np], bBaseHi + roff);
                ldsm_x4(bl[np], bBaseLo + roff);
            }
#pragma unroll
            for (int mt = 0; mt < 2; mt++)
#pragma unroll
                for (int nt = 0; nt < 8; nt++) {
                    const uint32_t* bhp = &bh[nt >> 1][(nt & 1) * 2];
                    const uint32_t* blp = &bl[nt >> 1][(nt & 1) * 2];
                    mma16816(acc[mt][nt], ah[mt], bhp);   // Ah*Bh
                    mma16816(acc[mt][nt], ah[mt], blp);   // Ah*Bl
                    mma16816(acc[mt][nt], al[mt], bhp);   // Al*Bh
                }
        }
    }

    // epilogue
    const int g  = lane >> 2;
    const int t2 = (lane & 3) * 2;
#pragma unroll
    for (int mt = 0; mt < 2; mt++) {
        int row0 = by * GBM + wm * 32 + mt * 16 + g;
#pragma unroll
        for (int nt = 0; nt < 8; nt++) {
            int col = bx * GBN + wn * 64 + nt * 8 + t2;
            *(float2*)(C + (size_t)row0 * N + col) =
                make_float2(acc[mt][nt][0], acc[mt][nt][1]);
            *(float2*)(C + (size_t)(row0 + 8) * N + col) =
                make_float2(acc[mt][nt][2], acc[mt][nt][3]);
        }
    }
}

// ======================= Flash attention (causal) ============================
#define FBM 64
#define FBN 64
#define QP  132
#define KP  132
#define VP  132
#define PP  65
#define SOFTMAX_SCALE 0.08838834764831845f   // 1/sqrt(128)

__global__ __launch_bounds__(256, 1)
void flash_kernel(const float* __restrict__ proj, float* __restrict__ ctx)
{
    extern __shared__ float smf[];
    float* Qs = smf;
    float* Ks = Qs + FBM * QP;
    float* Vs = Ks + FBN * KP;
    float* Ps = Vs + FBN * VP;

    const int q0  = blockIdx.x * FBM;
    const int h   = blockIdx.y;
    const int b   = blockIdx.z;
    const int tid = threadIdx.x;
    const int rg  = tid >> 4;
    const int cg  = tid & 15;
    const int r0  = rg * 4;
    const int d0  = cg * 4;

    for (int t = tid; t < FBM * 32; t += 256) {
        int r = t >> 5, kk = t & 31;
        const float* src = proj + (size_t)(b * SLEN + q0 + r) * H3 + h * HDIM;
        *(float4*)(Qs + r * QP + kk * 4) = *(const float4*)(src + kk * 4);
    }
    __syncthreads();

    float m[4], l[4], o[4][8];
#pragma unroll
    for (int i = 0; i < 4; i++) {
        m[i] = -FLT_MAX; l[i] = 0.f;
#pragma unroll
        for (int j = 0; j < 8; j++) o[i][j] = 0.f;
    }

    for (int k0 = 0; k0 <= q0; k0 += FBN) {
        for (int t = tid; t < FBN * 32; t += 256) {
            int c = t >> 5, kk = t & 31;
            const float* base = proj + (size_t)(b * SLEN + k0 + c) * H3 + h * HDIM;
            *(float4*)(Ks + c * KP + kk * 4) = *(const float4*)(base + HID   + kk * 4);
            *(float4*)(Vs + c * VP + kk * 4) = *(const float4*)(base + 2*HID + kk * 4);
        }
        __syncthreads();

        float acc[4][4];
#pragma unroll
        for (int i = 0; i < 4; i++)
#pragma unroll
            for (int j = 0; j < 4; j++) acc[i][j] = 0.f;

#pragma unroll 4
        for (int kk = 0; kk < 32; kk++) {
            float4 q4[4];
#pragma unroll
            for (int i = 0; i < 4; i++)
                q4[i] = *(const float4*)(Qs + (r0 + i) * QP + kk * 4);
#pragma unroll
            for (int j = 0; j < 4; j++) {
                float4 k4 = *(const float4*)(Ks + (cg + 16 * j) * KP + kk * 4);
#pragma unroll
                for (int i = 0; i < 4; i++) {
                    acc[i][j] += q4[i].x * k4.x + q4[i].y * k4.y
                               + q4[i].z * k4.z + q4[i].w * k4.w;
                }
            }
        }

        const bool diag = (k0 == q0);
#pragma unroll
        for (int i = 0; i < 4; i++)
#pragma unroll
            for (int j = 0; j < 4; j++) {
                acc[i][j] *= SOFTMAX_SCALE;
                if (diag) {
                    int qi = q0 + r0 + i;
                    int kj = k0 + cg + 16 * j;
                    if (kj > qi) acc[i][j] = -FLT_MAX;
                }
            }

        float p[4][4];
#pragma unroll
        for (int i = 0; i < 4; i++) {
            float tm = acc[i][0];
#pragma unroll
            for (int j = 1; j < 4; j++) tm = fmaxf(tm, acc[i][j]);
            tm = fmaxf(tm, __shfl_xor_sync(0xffffffffu, tm, 1));
            tm = fmaxf(tm, __shfl_xor_sync(0xffffffffu, tm, 2));
            tm = fmaxf(tm, __shfl_xor_sync(0xffffffffu, tm, 4));
            tm = fmaxf(tm, __shfl_xor_sync(0xffffffffu, tm, 8));
            float newm = fmaxf(m[i], tm);
            float alpha = __expf(m[i] - newm);
            m[i] = newm;
            float s = 0.f;
#pragma unroll
            for (int j = 0; j < 4; j++) {
                p[i][j] = __expf(acc[i][j] - newm);
                s += p[i][j];
            }
            s += __shfl_xor_sync(0xffffffffu, s, 1);
            s += __shfl_xor_sync(0xffffffffu, s, 2);
            s += __shfl_xor_sync(0xffffffffu, s, 4);
            s += __shfl_xor_sync(0xffffffffu, s, 8);
            l[i] = l[i] * alpha + s;
#pragma unroll
            for (int j = 0; j < 8; j++) o[i][j] *= alpha;
        }

#pragma unroll
        for (int i = 0; i < 4; i++)
#pragma unroll
            for (int j = 0; j < 4; j++)
                Ps[(r0 + i) * PP + cg + 16 * j] = p[i][j];
        __syncthreads();

#pragma unroll 2
        for (int c = 0; c < FBN; c++) {
            float pv[4];
#pragma unroll
            for (int i = 0; i < 4; i++) pv[i] = Ps[(r0 + i) * PP + c];
            float4 v0 = *(const float4*)(Vs + c * VP + d0);
            float4 v1 = *(const float4*)(Vs + c * VP + 64 + d0);
#pragma unroll
            for (int i = 0; i < 4; i++) {
                o[i][0] += pv[i] * v0.x; o[i][1] += pv[i] * v0.y;
                o[i][2] += pv[i] * v0.z; o[i][3] += pv[i] * v0.w;
                o[i][4] += pv[i] * v1.x; o[i][5] += pv[i] * v1.y;
                o[i][6] += pv[i] * v1.z; o[i][7] += pv[i] * v1.w;
            }
        }
        __syncthreads();
    }

#pragma unroll
    for (int i = 0; i < 4; i++) {
        float inv = 1.f / l[i];
        float* dst = ctx + (size_t)(b * SLEN + q0 + r0 + i) * HID + h * HDIM;
        *(float4*)(dst + d0)      = make_float4(o[i][0]*inv, o[i][1]*inv, o[i][2]*inv, o[i][3]*inv);
        *(float4*)(dst + 64 + d0) = make_float4(o[i][4]*inv, o[i][5]*inv, o[i][6]*inv, o[i][7]*inv);
    }
}

// ============================ host entry =====================================
extern "C" void kernel_launch(void* const* d_in, const int* in_sizes, int n_in,
                              void* d_out, int out_size)
{
    const float* hidden = (const float*)d_in[0];
    const float* w_pack = (const float*)d_in[2];
    const float* w_o    = (const float*)d_in[3];
    float* out = (float*)d_out;

    float *proj, *ctx;
    __nv_bfloat16 *ah, *al, *bh, *bl;
    cudaGetSymbolAddress((void**)&proj, g_proj);
    cudaGetSymbolAddress((void**)&ctx,  g_ctx);
    cudaGetSymbolAddress((void**)&ah,   g_ah);
    cudaGetSymbolAddress((void**)&al,   g_al);
    cudaGetSymbolAddress((void**)&bh,   g_bh);
    cudaGetSymbolAddress((void**)&bl,   g_bl);

    static bool attr_set = false;
    if (!attr_set) {
        cudaFuncSetAttribute(gemm_bf16s, cudaFuncAttributeMaxDynamicSharedMemorySize, GT_SMEM);
        int fsm = (FBM * QP + FBN * KP + FBN * VP + FBM * PP) * (int)sizeof(float);
        cudaFuncSetAttribute(flash_kernel, cudaFuncAttributeMaxDynamicSharedMemorySize, fsm);
        attr_set = true;
    }

    // 1) split inputs of QKV gemm
    {
        int nA = MROWS * HID, nB = H3 * HID;
        split_kernel<<<nA / 4 / 256, 256>>>(hidden, ah, al, nA);
        split_kernel<<<nB / 4 / 256, 256>>>(w_pack, bh, bl, nB);
    }
    // 2) QKV projection: proj[4096,6144]
    gemm_bf16s<<<dim3(H3 / GBN, MROWS / GBM), 256, GT_SMEM>>>(ah, al, bh, bl, proj, H3, HID);

    // 3) causal flash attention
    int fsm = (FBM * QP + FBN * KP + FBN * VP + FBM * PP) * (int)sizeof(float);
    flash_kernel<<<dim3(SLEN / FBM, NHEADS, BATCH), 256, fsm>>>(proj, ctx);

    // 4) split inputs of output gemm
    {
        int nA = MROWS * HID, nB = HID * HID;
        split_kernel<<<nA / 4 / 256, 256>>>(ctx, ah, al, nA);
        split_kernel<<<nB / 4 / 256, 256>>>(w_o, bh, bl, nB);
    }
    // 5) output projection: out[4096,2048]
    gemm_bf16s<<<dim3(HID / GBN, MROWS / GBM), 256, GT_SMEM>>>(ah, al, bh, bl, out, HID, HID);
}

// round 4
// speedup vs baseline: 1.5513x; 1.2447x over previous
#include <cuda_runtime.h>
#include <cuda_bf16.h>
#include <cfloat>
#include <cstdint>
#include <cstddef>

// Problem dims
#define BATCH   2
#define SLEN    2048
#define HID     2048
#define NHEADS  16
#define HDIM    128
#define H3      6144
#define MROWS   4096
#define SOFTMAX_SCALE 0.08838834764831845f   // 1/sqrt(128)

// ---------------- scratch (static device arrays; no allocations) -------------
__device__ float g_proj[(size_t)MROWS * H3];   // QKV projection output
__device__ float g_ctx [(size_t)MROWS * HID];  // attention context
__device__ __nv_bfloat16 g_ah[(size_t)MROWS * HID];
__device__ __nv_bfloat16 g_al[(size_t)MROWS * HID];
__device__ __nv_bfloat16 g_bh[(size_t)H3 * HID];
__device__ __nv_bfloat16 g_bl[(size_t)H3 * HID];

// ===================== small PTX helpers =====================================
__device__ __forceinline__ uint32_t smem_u32(const void* p) {
    uint32_t a;
    asm("{ .reg .u64 t; cvta.to.shared.u64 t, %1; cvt.u32.u64 %0, t; }"
        : "=r"(a) : "l"(p));
    return a;
}
__device__ __forceinline__ void cp_async16(uint32_t saddr, const void* gaddr) {
    asm volatile("cp.async.cg.shared.global [%0], [%1], 16;"
                 :: "r"(saddr), "l"(gaddr) : "memory");
}
__device__ __forceinline__ void cp_commit() {
    asm volatile("cp.async.commit_group;" ::: "memory");
}
template <int N>
__device__ __forceinline__ void cp_wait() {
    asm volatile("cp.async.wait_group %0;" :: "n"(N) : "memory");
}
__device__ __forceinline__ void ldsm_x4(uint32_t* r, uint32_t addr) {
    asm volatile("ldmatrix.sync.aligned.m8n8.x4.shared.b16 {%0,%1,%2,%3}, [%4];"
                 : "=r"(r[0]), "=r"(r[1]), "=r"(r[2]), "=r"(r[3]) : "r"(addr));
}
__device__ __forceinline__ void ldsm_x4_t(uint32_t* r, uint32_t addr) {
    asm volatile("ldmatrix.sync.aligned.m8n8.x4.trans.shared.b16 {%0,%1,%2,%3}, [%4];"
                 : "=r"(r[0]), "=r"(r[1]), "=r"(r[2]), "=r"(r[3]) : "r"(addr));
}
__device__ __forceinline__ void mma16816(float* c, const uint32_t* a, const uint32_t* b) {
    asm volatile(
        "mma.sync.aligned.m16n8k16.row.col.f32.bf16.bf16.f32 "
        "{%0,%1,%2,%3}, {%4,%5,%6,%7}, {%8,%9}, {%0,%1,%2,%3};"
        : "+f"(c[0]), "+f"(c[1]), "+f"(c[2]), "+f"(c[3])
        : "r"(a[0]), "r"(a[1]), "r"(a[2]), "r"(a[3]), "r"(b[0]), "r"(b[1]));
}
__device__ __forceinline__ void sts16(uint32_t addr, uint32_t a, uint32_t b,
                                      uint32_t c, uint32_t d) {
    asm volatile("st.shared.v4.b32 [%0], {%1,%2,%3,%4};"
                 :: "r"(addr), "r"(a), "r"(b), "r"(c), "r"(d) : "memory");
}
// load 8 fp32, scale, split to bf16 hi/lo, store 16B hi + 16B lo to smem
__device__ __forceinline__ void cvt8_sts(const float* src, float scale,
                                         uint32_t dhi, uint32_t dlo) {
    float4 v0 = *(const float4*)src;
    float4 v1 = *(const float4*)(src + 4);
    float x[8] = {v0.x, v0.y, v0.z, v0.w, v1.x, v1.y, v1.z, v1.w};
    uint32_t hp[4], lp[4];
#pragma unroll
    for (int j = 0; j < 4; j++) {
        float a = x[2*j] * scale, c = x[2*j+1] * scale;
        __nv_bfloat16 ha = __float2bfloat16_rn(a);
        __nv_bfloat16 hb = __float2bfloat16_rn(c);
        __nv_bfloat16 la = __float2bfloat16_rn(a - __bfloat162float(ha));
        __nv_bfloat16 lb = __float2bfloat16_rn(c - __bfloat162float(hb));
        __nv_bfloat162 h2 = __nv_bfloat162(ha, hb);
        __nv_bfloat162 l2 = __nv_bfloat162(la, lb);
        hp[j] = *(uint32_t*)&h2;
        lp[j] = *(uint32_t*)&l2;
    }
    sts16(dhi, hp[0], hp[1], hp[2], hp[3]);
    sts16(dlo, lp[0], lp[1], lp[2], lp[3]);
}

// ================= fp32 -> bf16 hi/lo split (elementwise) ====================
__global__ __launch_bounds__(256)
void split_kernel(const float* __restrict__ src, __nv_bfloat16* __restrict__ hi,
                  __nv_bfloat16* __restrict__ lo, int n)
{
    int i4 = blockIdx.x * blockDim.x + threadIdx.x;
    if (i4 * 4 >= n) return;
    float4 v = *(const float4*)(src + i4 * 4);
    float x[4] = {v.x, v.y, v.z, v.w};
    __nv_bfloat16 h[4], l[4];
#pragma unroll
    for (int j = 0; j < 4; j++) {
        h[j] = __float2bfloat16_rn(x[j]);
        l[j] = __float2bfloat16_rn(x[j] - __bfloat162float(h[j]));
    }
    ushort4 hp, lp;
    hp.x = *(uint16_t*)&h[0]; hp.y = *(uint16_t*)&h[1];
    hp.z = *(uint16_t*)&h[2]; hp.w = *(uint16_t*)&h[3];
    lp.x = *(uint16_t*)&l[0]; lp.y = *(uint16_t*)&l[1];
    lp.z = *(uint16_t*)&l[2]; lp.w = *(uint16_t*)&l[3];
    *(ushort4*)(hi + i4 * 4) = hp;
    *(ushort4*)(lo + i4 * 4) = lp;
}

// ========== tensor-core GEMM: C[M,N] = A[M,K] * B[N,K]^T, fp32 out ==========
#define GBM 128
#define GBN 128
#define GBK 32
#define MAT_BYTES 8192
#define STAGE_BYTES 32768
#define GT_SMEM (2 * STAGE_BYTES)

__global__ __launch_bounds__(256, 1)
void gemm_bf16s(const __nv_bfloat16* __restrict__ Ah, const __nv_bfloat16* __restrict__ Al,
                const __nv_bfloat16* __restrict__ Bh, const __nv_bfloat16* __restrict__ Bl,
                float* __restrict__ C, int N, int K)
{
    extern __shared__ char sm[];
    const uint32_t sbase = smem_u32(sm);
    const int tid  = threadIdx.x;
    const int wid  = tid >> 5;
    const int lane = tid & 31;
    const int bx = blockIdx.x;
    const int by = blockIdx.y;
    const int wm = wid >> 1;
    const int wn = wid & 1;

    const __nv_bfloat16* gsrc[4] = {
        Ah + (size_t)by * GBM * K, Al + (size_t)by * GBM * K,
        Bh + (size_t)bx * GBN * K, Bl + (size_t)bx * GBN * K };

    auto prefetch = [&](int c) {
        const int stage = c & 1;
        const uint32_t sst = sbase + stage * STAGE_BYTES;
        const int k0 = c * GBK;
#pragma unroll
        for (int i = 0; i < 8; i++) {
            int idx = i * 256 + tid;
            int mat = idx >> 9;
            int within = idx & 511;
            int row = within >> 2;
            int kc = within & 3;
            const __nv_bfloat16* g = gsrc[mat] + (size_t)row * K + k0 + kc * 8;
            uint32_t s = sst + mat * MAT_BYTES + kc * 2048 + row * 16;
            cp_async16(s, g);
        }
        cp_commit();
    };

    const int subA = lane >> 3;
    const int rowoffA = (lane & 7) + (subA & 1) * 8;
    const int kcselA  = subA >> 1;
    const int rowoffB = (lane & 7) + ((lane >> 4) * 8);
    const int kcselB  = (lane >> 3) & 1;

    float acc[2][8][4];
#pragma unroll
    for (int mt = 0; mt < 2; mt++)
#pragma unroll
        for (int nt = 0; nt < 8; nt++)
#pragma unroll
            for (int q = 0; q < 4; q++) acc[mt][nt][q] = 0.f;

    const int KC = K / GBK;
    prefetch(0);

    for (int c = 0; c < KC; c++) {
        __syncthreads();
        if (c + 1 < KC) { prefetch(c + 1); cp_wait<1>(); }
        else            { cp_wait<0>(); }
        __syncthreads();

        const uint32_t sst = sbase + (c & 1) * STAGE_BYTES;
        const uint32_t aBaseHi = sst + 0 * MAT_BYTES;
        const uint32_t aBaseLo = sst + 1 * MAT_BYTES;
        const uint32_t bBaseHi = sst + 2 * MAT_BYTES;
        const uint32_t bBaseLo = sst + 3 * MAT_BYTES;

#pragma unroll
        for (int ks = 0; ks < 2; ks++) {
            uint32_t ah[2][4], al[2][4], bh[4][4], bl[4][4];
#pragma unroll
            for (int mt = 0; mt < 2; mt++) {
                uint32_t roff = (uint32_t)((ks * 2 + kcselA) * 2048 +
                                           (wm * 32 + mt * 16 + rowoffA) * 16);
                ldsm_x4(ah[mt], aBaseHi + roff);
                ldsm_x4(al[mt], aBaseLo + roff);
            }
#pragma unroll
            for (int np = 0; np < 4; np++) {
                uint32_t roff = (uint32_t)((ks * 2 + kcselB) * 2048 +
                                           (wn * 64 + np * 16 + rowoffB) * 16);
                ldsm_x4(bh[np], bBaseHi + roff);
                ldsm_x4(bl[np], bBaseLo + roff);
            }
#pragma unroll
            for (int mt = 0; mt < 2; mt++)
#pragma unroll
                for (int nt = 0; nt < 8; nt++) {
                    const uint32_t* bhp = &bh[nt >> 1][(nt & 1) * 2];
                    const uint32_t* blp = &bl[nt >> 1][(nt & 1) * 2];
                    mma16816(acc[mt][nt], ah[mt], bhp);
                    mma16816(acc[mt][nt], ah[mt], blp);
                    mma16816(acc[mt][nt], al[mt], bhp);
                }
        }
    }

    const int g  = lane >> 2;
    const int t2 = (lane & 3) * 2;
#pragma unroll
    for (int mt = 0; mt < 2; mt++) {
        int row0 = by * GBM + wm * 32 + mt * 16 + g;
#pragma unroll
        for (int nt = 0; nt < 8; nt++) {
            int col = bx * GBN + wn * 64 + nt * 8 + t2;
            *(float2*)(C + (size_t)row0 * N + col) =
                make_float2(acc[mt][nt][0], acc[mt][nt][1]);
            *(float2*)(C + (size_t)(row0 + 8) * N + col) =
                make_float2(acc[mt][nt][2], acc[mt][nt][3]);
        }
    }
}

// ============== tensor-core causal flash attention ===========================
// CTA: 64 q-rows, 4 warps (16 rows each), BN=64 keys/iter, HD=128.
// Q pre-scaled by 1/sqrt(128), Markidis split everywhere.
// smem: QH QL KH KL VH VL, each [kcg(16)][row(64)][16B] = 16KB  -> 96KB
#define FA_SMEM 98304

__global__ __launch_bounds__(128, 1)
void flash_tc(const float* __restrict__ proj, float* __restrict__ ctx)
{
    extern __shared__ char smc[];
    const uint32_t sb = smem_u32(smc);
    const uint32_t sQH = sb,          sQL = sb + 16384;
    const uint32_t sKH = sb + 32768,  sKL = sb + 49152;
    const uint32_t sVH = sb + 65536,  sVL = sb + 81920;

    const int tid  = threadIdx.x;
    const int lane = tid & 31;
    const int wm   = tid >> 5;                 // warp 0..3 -> rows wm*16..
    const int q0   = (int)(gridDim.x - 1 - blockIdx.x) * 64;  // heavy tiles first
    const int h    = blockIdx.y;
    const int b    = blockIdx.z;
    const int g    = lane >> 2;
    const int t2   = (lane & 3) * 2;

    // ---- stage Q (scaled) into smem ----
#pragma unroll
    for (int i = 0; i < 8; i++) {
        int item = i * 128 + tid;              // 1024 = 64 rows x 16 kcg
        int row = item >> 4, kcg = item & 15;
        const float* src = proj + (size_t)(b * SLEN + q0 + row) * H3 + h * HDIM + kcg * 8;
        cvt8_sts(src, SOFTMAX_SCALE,
                 sQH + kcg * 1024 + row * 16, sQL + kcg * 1024 + row * 16);
    }
    __syncthreads();

    const int rowoffA = (lane & 7) + ((lane >> 3) & 1) * 8;
    const int kcselA  = lane >> 4;
    const int rowoffB = (lane & 7) + (lane >> 4) * 8;
    const int kcselB  = (lane >> 3) & 1;

    // ---- Q fragments to registers (reused across all key tiles) ----
    uint32_t qh[8][4], ql[8][4];
#pragma unroll
    for (int k = 0; k < 8; k++) {
        uint32_t roff = (uint32_t)((2 * k + kcselA) * 1024 + (wm * 16 + rowoffA) * 16);
        ldsm_x4(qh[k], sQH + roff);
        ldsm_x4(ql[k], sQL + roff);
    }

    float m1 = -FLT_MAX, m2 = -FLT_MAX, l1 = 0.f, l2 = 0.f;
    float o[16][4];
#pragma unroll
    for (int nt = 0; nt < 16; nt++)
#pragma unroll
        for (int q = 0; q < 4; q++) o[nt][q] = 0.f;

    for (int k0 = 0; k0 <= q0; k0 += 64) {
        __syncthreads();   // everyone done reading previous K/V
        // ---- stage K and V tiles (bf16 hi/lo) ----
#pragma unroll
        for (int i = 0; i < 16; i++) {
            int item = i * 128 + tid;          // 2048 = 2 mats x 64 x 16
            int mat = item >> 10;              // 0 = K, 1 = V
            int within = item & 1023;
            int row = within >> 4, kcg = within & 15;
            const float* src = proj + (size_t)(b * SLEN + k0 + row) * H3
                             + h * HDIM + (1 + mat) * HID + kcg * 8;
            uint32_t hbase = (mat ? sVH : sKH) + kcg * 1024 + row * 16;
            cvt8_sts(src, 1.0f, hbase, hbase + 16384);
        }
        __syncthreads();

        // ---- S = Q K^T (scaled), 3-product split ----
        float s[8][4];
#pragma unroll
        for (int nt = 0; nt < 8; nt++)
#pragma unroll
            for (int q = 0; q < 4; q++) s[nt][q] = 0.f;

#pragma unroll
        for (int k = 0; k < 8; k++) {
#pragma unroll
            for (int np = 0; np < 4; np++) {
                uint32_t roff = (uint32_t)((2 * k + kcselB) * 1024 + (np * 16 + rowoffB) * 16);
                uint32_t kh4[4], kl4[4];
                ldsm_x4(kh4, sKH + roff);
                ldsm_x4(kl4, sKL + roff);
#pragma unroll
                for (int sub = 0; sub < 2; sub++) {
                    int nt = np * 2 + sub;
                    mma16816(s[nt], qh[k], &kh4[sub * 2]);
                    mma16816(s[nt], qh[k], &kl4[sub * 2]);
                    mma16816(s[nt], ql[k], &kh4[sub * 2]);
                }
            }
        }

        // ---- causal mask on the diagonal tile ----
        if (k0 == q0) {
            int r1 = q0 + wm * 16 + g, r2 = r1 + 8;
#pragma unroll
            for (int nt = 0; nt < 8; nt++) {
                int c0 = k0 + nt * 8 + t2;
                if (c0     > r1) s[nt][0] = -FLT_MAX;
                if (c0 + 1 > r1) s[nt][1] = -FLT_MAX;
                if (c0     > r2) s[nt][2] = -FLT_MAX;
                if (c0 + 1 > r2) s[nt][3] = -FLT_MAX;
            }
        }

        // ---- online softmax (rows g and g+8) ----
        float tm1 = -FLT_MAX, tm2 = -FLT_MAX;
#pragma unroll
        for (int nt = 0; nt < 8; nt++) {
            tm1 = fmaxf(tm1, fmaxf(s[nt][0], s[nt][1]));
            tm2 = fmaxf(tm2, fmaxf(s[nt][2], s[nt][3]));
        }
        tm1 = fmaxf(tm1, __shfl_xor_sync(0xffffffffu, tm1, 1));
        tm1 = fmaxf(tm1, __shfl_xor_sync(0xffffffffu, tm1, 2));
        tm2 = fmaxf(tm2, __shfl_xor_sync(0xffffffffu, tm2, 1));
        tm2 = fmaxf(tm2, __shfl_xor_sync(0xffffffffu, tm2, 2));
        float nm1 = fmaxf(m1, tm1), nm2 = fmaxf(m2, tm2);
        float a1 = __expf(m1 - nm1), a2 = __expf(m2 - nm2);
        m1 = nm1; m2 = nm2;

        float rs1 = 0.f, rs2 = 0.f;
#pragma unroll
        for (int nt = 0; nt < 8; nt++) {
            s[nt][0] = __expf(s[nt][0] - nm1);
            s[nt][1] = __expf(s[nt][1] - nm1);
            s[nt][2] = __expf(s[nt][2] - nm2);
            s[nt][3] = __expf(s[nt][3] - nm2);
            rs1 += s[nt][0] + s[nt][1];
            rs2 += s[nt][2] + s[nt][3];
        }
        rs1 += __shfl_xor_sync(0xffffffffu, rs1, 1);
        rs1 += __shfl_xor_sync(0xffffffffu, rs1, 2);
        rs2 += __shfl_xor_sync(0xffffffffu, rs2, 1);
        rs2 += __shfl_xor_sync(0xffffffffu, rs2, 2);
        l1 = l1 * a1 + rs1;
        l2 = l2 * a2 + rs2;
#pragma unroll
        for (int nt = 0; nt < 16; nt++) {
            o[nt][0] *= a1; o[nt][1] *= a1;
            o[nt][2] *= a2; o[nt][3] *= a2;
        }

        // ---- P -> bf16 hi/lo fragments (in registers) ----
        uint32_t hp01[8], hp23[8], lp01[8], lp23[8];
#pragma unroll
        for (int nt = 0; nt < 8; nt++) {
            __nv_bfloat16 h0 = __float2bfloat16_rn(s[nt][0]);
            __nv_bfloat16 h1 = __float2bfloat16_rn(s[nt][1]);
            __nv_bfloat16 h2 = __float2bfloat16_rn(s[nt][2]);
            __nv_bfloat16 h3 = __float2bfloat16_rn(s[nt][3]);
            __nv_bfloat16 e0 = __float2bfloat16_rn(s[nt][0] - __bfloat162float(h0));
            __nv_bfloat16 e1 = __float2bfloat16_rn(s[nt][1] - __bfloat162float(h1));
            __nv_bfloat16 e2 = __float2bfloat16_rn(s[nt][2] - __bfloat162float(h2));
            __nv_bfloat16 e3 = __float2bfloat16_rn(s[nt][3] - __bfloat162float(h3));
            __nv_bfloat162 a01 = __nv_bfloat162(h0, h1), a23 = __nv_bfloat162(h2, h3);
            __nv_bfloat162 b01 = __nv_bfloat162(e0, e1), b23 = __nv_bfloat162(e2, e3);
            hp01[nt] = *(uint32_t*)&a01; hp23[nt] = *(uint32_t*)&a23;
            lp01[nt] = *(uint32_t*)&b01; lp23[nt] = *(uint32_t*)&b23;
        }

        // ---- O += P V  (V via ldmatrix.trans, 3-product split) ----
#pragma unroll
        for (int kt = 0; kt < 4; kt++) {
            uint32_t ah4[4] = {hp01[2*kt], hp23[2*kt], hp01[2*kt+1], hp23[2*kt+1]};
            uint32_t al4[4] = {lp01[2*kt], lp23[2*kt], lp01[2*kt+1], lp23[2*kt+1]};
#pragma unroll
            for (int np = 0; np < 8; np++) {
                uint32_t roff = (uint32_t)((np * 2 + (lane >> 4)) * 1024 +
                                           (kt * 16 + ((lane >> 3) & 1) * 8 + (lane & 7)) * 16);
                uint32_t vh4[4], vl4[4];
                ldsm_x4_t(vh4, sVH + roff);
                ldsm_x4_t(vl4, sVL + roff);
#pragma unroll
                for (int sub = 0; sub < 2; sub++) {
                    int nt = np * 2 + sub;
                    mma16816(o[nt], ah4, &vh4[sub * 2]);
                    mma16816(o[nt], ah4, &vl4[sub * 2]);
                    mma16816(o[nt], al4, &vh4[sub * 2]);
                }
            }
        }
    }

    // ---- finalize ----
    float inv1 = 1.f / l1, inv2 = 1.f / l2;
    int r1 = q0 + wm * 16 + g;
    float* d1 = ctx + (size_t)(b * SLEN + r1) * HID + h * HDIM;
    float* d2 = d1 + 8 * HID;
#pragma unroll
    for (int nt = 0; nt < 16; nt++) {
        int col = nt * 8 + t2;
        *(float2*)(d1 + col) = make_float2(o[nt][0] * inv1, o[nt][1] * inv1);
        *(float2*)(d2 + col) = make_float2(o[nt][2] * inv2, o[nt][3] * inv2);
    }
}

// ============================ host entry =====================================
extern "C" void kernel_launch(void* const* d_in, const int* in_sizes, int n_in,
                              void* d_out, int out_size)
{
    const float* hidden = (const float*)d_in[0];
    const float* w_pack = (const float*)d_in[2];
    const float* w_o    = (const float*)d_in[3];
    float* out = (float*)d_out;

    float *proj, *ctx;
    __nv_bfloat16 *ah, *al, *bh, *bl;
    cudaGetSymbolAddress((void**)&proj, g_proj);
    cudaGetSymbolAddress((void**)&ctx,  g_ctx);
    cudaGetSymbolAddress((void**)&ah,   g_ah);
    cudaGetSymbolAddress((void**)&al,   g_al);
    cudaGetSymbolAddress((void**)&bh,   g_bh);
    cudaGetSymbolAddress((void**)&bl,   g_bl);

    static bool attr_set = false;
    if (!attr_set) {
        cudaFuncSetAttribute(gemm_bf16s, cudaFuncAttributeMaxDynamicSharedMemorySize, GT_SMEM);
        cudaFuncSetAttribute(flash_tc,   cudaFuncAttributeMaxDynamicSharedMemorySize, FA_SMEM);
        attr_set = true;
    }

    // 1) split inputs of QKV gemm
    {
        int nA = MROWS * HID, nB = H3 * HID;
        split_kernel<<<nA / 4 / 256, 256>>>(hidden, ah, al, nA);
        split_kernel<<<nB / 4 / 256, 256>>>(w_pack, bh, bl, nB);
    }
    // 2) QKV projection
    gemm_bf16s<<<dim3(H3 / GBN, MROWS / GBM), 256, GT_SMEM>>>(ah, al, bh, bl, proj, H3, HID);

    // 3) causal flash attention (tensor cores)
    flash_tc<<<dim3(SLEN / 64, NHEADS, BATCH), 128, FA_SMEM>>>(proj, ctx);

    // 4) split inputs of output gemm
    {
        int nA = MROWS * HID, nB = HID * HID;
        split_kernel<<<nA / 4 / 256, 256>>>(ctx, ah, al, nA);
        split_kernel<<<nB / 4 / 256, 256>>>(w_o, bh, bl, nB);
    }
    // 5) output projection
    gemm_bf16s<<<dim3(HID / GBN, MROWS / GBM), 256, GT_SMEM>>>(ah, al, bh, bl, out, HID, HID);
}

// round 5
// speedup vs baseline: 1.6564x; 1.0678x over previous
#include <cuda_runtime.h>
#include <cuda_bf16.h>
#include <cfloat>
#include <cstdint>
#include <cstddef>

// Problem dims
#define BATCH   2
#define SLEN    2048
#define HID     2048
#define NHEADS  16
#define HDIM    128
#define H3      6144
#define MROWS   4096
#define SOFTMAX_SCALE 0.08838834764831845f   // 1/sqrt(128)

// ---------------- scratch (static device arrays; no allocations) -------------
__device__ __nv_bfloat16 g_ph[(size_t)MROWS * H3];    // proj hi (bf16)
__device__ __nv_bfloat16 g_pl[(size_t)MROWS * H3];    // proj lo
__device__ __nv_bfloat16 g_ch[(size_t)MROWS * HID];   // ctx hi
__device__ __nv_bfloat16 g_cl[(size_t)MROWS * HID];   // ctx lo
__device__ __nv_bfloat16 g_ah[(size_t)MROWS * HID];   // gemm A hi
__device__ __nv_bfloat16 g_al[(size_t)MROWS * HID];
__device__ __nv_bfloat16 g_bh[(size_t)H3 * HID];      // gemm B hi
__device__ __nv_bfloat16 g_bl[(size_t)H3 * HID];

// ===================== small PTX helpers =====================================
__device__ __forceinline__ uint32_t smem_u32(const void* p) {
    uint32_t a;
    asm("{ .reg .u64 t; cvta.to.shared.u64 t, %1; cvt.u32.u64 %0, t; }"
        : "=r"(a) : "l"(p));
    return a;
}
__device__ __forceinline__ void cp_async16(uint32_t saddr, const void* gaddr) {
    asm volatile("cp.async.cg.shared.global [%0], [%1], 16;"
                 :: "r"(saddr), "l"(gaddr) : "memory");
}
__device__ __forceinline__ void cp_commit() {
    asm volatile("cp.async.commit_group;" ::: "memory");
}
template <int N>
__device__ __forceinline__ void cp_wait() {
    asm volatile("cp.async.wait_group %0;" :: "n"(N) : "memory");
}
__device__ __forceinline__ void ldsm_x4(uint32_t* r, uint32_t addr) {
    asm volatile("ldmatrix.sync.aligned.m8n8.x4.shared.b16 {%0,%1,%2,%3}, [%4];"
                 : "=r"(r[0]), "=r"(r[1]), "=r"(r[2]), "=r"(r[3]) : "r"(addr));
}
__device__ __forceinline__ void ldsm_x4_t(uint32_t* r, uint32_t addr) {
    asm volatile("ldmatrix.sync.aligned.m8n8.x4.trans.shared.b16 {%0,%1,%2,%3}, [%4];"
                 : "=r"(r[0]), "=r"(r[1]), "=r"(r[2]), "=r"(r[3]) : "r"(addr));
}
__device__ __forceinline__ void mma16816(float* c, const uint32_t* a, const uint32_t* b) {
    asm volatile(
        "mma.sync.aligned.m16n8k16.row.col.f32.bf16.bf16.f32 "
        "{%0,%1,%2,%3}, {%4,%5,%6,%7}, {%8,%9}, {%0,%1,%2,%3};"
        : "+f"(c[0]), "+f"(c[1]), "+f"(c[2]), "+f"(c[3])
        : "r"(a[0]), "r"(a[1]), "r"(a[2]), "r"(a[3]), "r"(b[0]), "r"(b[1]));
}
__device__ __forceinline__ void split2(float a, float b, uint32_t& hi, uint32_t& lo) {
    __nv_bfloat16 ha = __float2bfloat16_rn(a);
    __nv_bfloat16 hb = __float2bfloat16_rn(b);
    __nv_bfloat16 la = __float2bfloat16_rn(a - __bfloat162float(ha));
    __nv_bfloat16 lb = __float2bfloat16_rn(b - __bfloat162float(hb));
    __nv_bfloat162 h2 = __nv_bfloat162(ha, hb);
    __nv_bfloat162 l2 = __nv_bfloat162(la, lb);
    hi = *(uint32_t*)&h2;
    lo = *(uint32_t*)&l2;
}

// ================= fp32 -> bf16 hi/lo split (elementwise) ====================
__global__ __launch_bounds__(256)
void split_kernel(const float* __restrict__ src, __nv_bfloat16* __restrict__ hi,
                  __nv_bfloat16* __restrict__ lo, int n)
{
    int i4 = blockIdx.x * blockDim.x + threadIdx.x;
    if (i4 * 4 >= n) return;
    float4 v = *(const float4*)(src + i4 * 4);
    uint32_t h0, l0, h1, l1;
    split2(v.x, v.y, h0, l0);
    split2(v.z, v.w, h1, l1);
    *(uint2*)(hi + i4 * 4) = make_uint2(h0, h1);
    *(uint2*)(lo + i4 * 4) = make_uint2(l0, l1);
}

// ========== tensor-core GEMM: C[M,N] = A[M,K] * B[N,K]^T =====================
// OM=0: fp32 C.   OM=1: bf16 hi/lo C (Markidis re-split for next stage).
// BM=BN=128, BK=32, 256 thr, 8 warps 4x2, 3-stage cp.async pipeline.
#define GBM 128
#define GBN 128
#define GBK 32
#define MAT_BYTES 8192
#define STAGE_BYTES 32768
#define GT_SMEM (3 * STAGE_BYTES)

template <int OM>
__global__ __launch_bounds__(256, 1)
void gemm_bf16s(const __nv_bfloat16* __restrict__ Ah, const __nv_bfloat16* __restrict__ Al,
                const __nv_bfloat16* __restrict__ Bh, const __nv_bfloat16* __restrict__ Bl,
                float* __restrict__ C, __nv_bfloat16* __restrict__ Ch,
                __nv_bfloat16* __restrict__ Cl, int N, int K)
{
    extern __shared__ char sm[];
    const uint32_t sbase = smem_u32(sm);
    const int tid  = threadIdx.x;
    const int wid  = tid >> 5;
    const int lane = tid & 31;
    const int bx = blockIdx.x;
    const int by = blockIdx.y;
    const int wm = wid >> 1;
    const int wn = wid & 1;

    const __nv_bfloat16* gsrc[4] = {
        Ah + (size_t)by * GBM * K, Al + (size_t)by * GBM * K,
        Bh + (size_t)bx * GBN * K, Bl + (size_t)bx * GBN * K };

    // idx -> mat(2b), kc(2b), row(7b); row fastest => conflict-free smem stores
    auto prefetch = [&](int c) {
        const uint32_t sst = sbase + (uint32_t)(c % 3) * STAGE_BYTES;
        const int k0 = c * GBK;
#pragma unroll
        for (int i = 0; i < 8; i++) {
            int idx = i * 256 + tid;
            int mat = idx >> 9;
            int within = idx & 511;
            int kc  = within >> 7;
            int row = within & 127;
            const __nv_bfloat16* g = gsrc[mat] + (size_t)row * K + k0 + kc * 8;
            uint32_t s = sst + mat * MAT_BYTES + kc * 2048 + row * 16;
            cp_async16(s, g);
        }
        cp_commit();
    };

    const int subA = lane >> 3;
    const int rowoffA = (lane & 7) + (subA & 1) * 8;
    const int kcselA  = subA >> 1;
    const int rowoffB = (lane & 7) + ((lane >> 4) * 8);
    const int kcselB  = (lane >> 3) & 1;

    float acc[2][8][4];
#pragma unroll
    for (int mt = 0; mt < 2; mt++)
#pragma unroll
        for (int nt = 0; nt < 8; nt++)
#pragma unroll
            for (int q = 0; q < 4; q++) acc[mt][nt][q] = 0.f;

    const int KC = K / GBK;
    prefetch(0);
    prefetch(1);

    for (int c = 0; c < KC; c++) {
        cp_wait<1>();
        __syncthreads();
        if (c + 2 < KC) prefetch(c + 2);

        const uint32_t sst = sbase + (uint32_t)(c % 3) * STAGE_BYTES;
        const uint32_t aBaseHi = sst + 0 * MAT_BYTES;
        const uint32_t aBaseLo = sst + 1 * MAT_BYTES;
        const uint32_t bBaseHi = sst + 2 * MAT_BYTES;
        const uint32_t bBaseLo = sst + 3 * MAT_BYTES;

#pragma unroll
        for (int ks = 0; ks < 2; ks++) {
            uint32_t ah[2][4], al[2][4], bh[4][4], bl[4][4];
#pragma unroll
            for (int mt = 0; mt < 2; mt++) {
                uint32_t roff = (uint32_t)((ks * 2 + kcselA) * 2048 +
                                           (wm * 32 + mt * 16 + rowoffA) * 16);
                ldsm_x4(ah[mt], aBaseHi + roff);
                ldsm_x4(al[mt], aBaseLo + roff);
            }
#pragma unroll
            for (int np = 0; np < 4; np++) {
                uint32_t roff = (uint32_t)((ks * 2 + kcselB) * 2048 +
                                           (wn * 64 + np * 16 + rowoffB) * 16);
                ldsm_x4(bh[np], bBaseHi + roff);
                ldsm_x4(bl[np], bBaseLo + roff);
            }
#pragma unroll
            for (int mt = 0; mt < 2; mt++)
#pragma unroll
                for (int nt = 0; nt < 8; nt++) {
                    const uint32_t* bhp = &bh[nt >> 1][(nt & 1) * 2];
                    const uint32_t* blp = &bl[nt >> 1][(nt & 1) * 2];
                    mma16816(acc[mt][nt], ah[mt], bhp);
                    mma16816(acc[mt][nt], ah[mt], blp);
                    mma16816(acc[mt][nt], al[mt], bhp);
                }
        }
        __syncthreads();
    }

    const int g  = lane >> 2;
    const int t2 = (lane & 3) * 2;
#pragma unroll
    for (int mt = 0; mt < 2; mt++) {
        int row0 = by * GBM + wm * 32 + mt * 16 + g;
#pragma unroll
        for (int nt = 0; nt < 8; nt++) {
            int col = bx * GBN + wn * 64 + nt * 8 + t2;
            if (OM == 0) {
                *(float2*)(C + (size_t)row0 * N + col) =
                    make_float2(acc[mt][nt][0], acc[mt][nt][1]);
                *(float2*)(C + (size_t)(row0 + 8) * N + col) =
                    make_float2(acc[mt][nt][2], acc[mt][nt][3]);
            } else {
                uint32_t h0, l0, h1, l1;
                split2(acc[mt][nt][0], acc[mt][nt][1], h0, l0);
                split2(acc[mt][nt][2], acc[mt][nt][3], h1, l1);
                *(uint32_t*)(Ch + (size_t)row0 * N + col) = h0;
                *(uint32_t*)(Cl + (size_t)row0 * N + col) = l0;
                *(uint32_t*)(Ch + (size_t)(row0 + 8) * N + col) = h1;
                *(uint32_t*)(Cl + (size_t)(row0 + 8) * N + col) = l1;
            }
        }
    }
}

// ============== tensor-core causal flash attention (bf16 hi/lo in) ===========
// CTA: 64 q-rows, 4 warps. BN=64 keys/iter. Inputs pre-split bf16.
// smem: QH QL KH KL VH VL each [kcg(16)][row(64)][16B] = 16KB -> 96KB, 2 CTA/SM
#define FA_SMEM 98304

__global__ __launch_bounds__(128, 1)
void flash_tc(const __nv_bfloat16* __restrict__ ph, const __nv_bfloat16* __restrict__ pl,
              __nv_bfloat16* __restrict__ ch, __nv_bfloat16* __restrict__ cl)
{
    extern __shared__ char smc[];
    const uint32_t sb = smem_u32(smc);
    const uint32_t sQH = sb,          sQL = sb + 16384;
    const uint32_t sKH = sb + 32768,  sKL = sb + 49152;
    const uint32_t sVH = sb + 65536,  sVL = sb + 81920;

    const int tid  = threadIdx.x;
    const int lane = tid & 31;
    const int wm   = tid >> 5;
    const int q0   = (int)(gridDim.x - 1 - blockIdx.x) * 64;
    const int h    = blockIdx.y;
    const int b    = blockIdx.z;
    const int g    = lane >> 2;
    const int t2   = (lane & 3) * 2;

    const size_t rowbase = (size_t)(b * SLEN) * H3 + h * HDIM;

    // ---- Q loads (group 0) ----
#pragma unroll
    for (int i = 0; i < 16; i++) {
        int item = i * 128 + tid;            // 2048 = 2 mats x 16 kcg x 64 rows
        int mat = item >> 10;
        int within = item & 1023;
        int kcg = within >> 6;
        int row = within & 63;
        const __nv_bfloat16* src = (mat ? pl : ph) + rowbase + (size_t)(q0 + row) * H3 + kcg * 8;
        cp_async16((mat ? sQL : sQH) + kcg * 1024 + row * 16, src);
    }
    cp_commit();
    // ---- K tile 0 loads (group 1) ----
#pragma unroll
    for (int i = 0; i < 16; i++) {
        int item = i * 128 + tid;
        int mat = item >> 10;
        int within = item & 1023;
        int kcg = within >> 6;
        int row = within & 63;
        const __nv_bfloat16* src = (mat ? pl : ph) + rowbase + (size_t)row * H3 + HID + kcg * 8;
        cp_async16((mat ? sKL : sKH) + kcg * 1024 + row * 16, src);
    }
    cp_commit();

    cp_wait<1>();          // Q ready
    __syncthreads();

    const int rowoffA = (lane & 7) + ((lane >> 3) & 1) * 8;
    const int kcselA  = lane >> 4;
    const int rowoffB = (lane & 7) + (lane >> 4) * 8;
    const int kcselB  = (lane >> 3) & 1;

    uint32_t qh[8][4], ql[8][4];
#pragma unroll
    for (int k = 0; k < 8; k++) {
        uint32_t roff = (uint32_t)((2 * k + kcselA) * 1024 + (wm * 16 + rowoffA) * 16);
        ldsm_x4(qh[k], sQH + roff);
        ldsm_x4(ql[k], sQL + roff);
    }

    float m1 = -FLT_MAX, m2 = -FLT_MAX, l1 = 0.f, l2 = 0.f;
    float o[16][4];
#pragma unroll
    for (int nt = 0; nt < 16; nt++)
#pragma unroll
        for (int q = 0; q < 4; q++) o[nt][q] = 0.f;

    for (int k0 = 0; k0 <= q0; k0 += 64) {
        // ---- V loads for this tile (committed after K of this tile) ----
#pragma unroll
        for (int i = 0; i < 16; i++) {
            int item = i * 128 + tid;
            int mat = item >> 10;
            int within = item & 1023;
            int kcg = within >> 6;
            int row = within & 63;
            const __nv_bfloat16* src = (mat ? pl : ph) + rowbase +
                                       (size_t)(k0 + row) * H3 + 2 * HID + kcg * 8;
            cp_async16((mat ? sVL : sVH) + kcg * 1024 + row * 16, src);
        }
        cp_commit();

        cp_wait<1>();      // K ready (V may be in flight)
        __syncthreads();

        // ---- S = Q K^T, 3-product split ----
        float s[8][4];
#pragma unroll
        for (int nt = 0; nt < 8; nt++)
#pragma unroll
            for (int q = 0; q < 4; q++) s[nt][q] = 0.f;

#pragma unroll
        for (int k = 0; k < 8; k++) {
#pragma unroll
            for (int np = 0; np < 4; np++) {
                uint32_t roff = (uint32_t)((2 * k + kcselB) * 1024 + (np * 16 + rowoffB) * 16);
                uint32_t kh4[4], kl4[4];
                ldsm_x4(kh4, sKH + roff);
                ldsm_x4(kl4, sKL + roff);
#pragma unroll
                for (int sub = 0; sub < 2; sub++) {
                    int nt = np * 2 + sub;
                    mma16816(s[nt], qh[k], &kh4[sub * 2]);
                    mma16816(s[nt], qh[k], &kl4[sub * 2]);
                    mma16816(s[nt], ql[k], &kh4[sub * 2]);
                }
            }
        }

        // ---- scale + causal mask ----
#pragma unroll
        for (int nt = 0; nt < 8; nt++)
#pragma unroll
            for (int q = 0; q < 4; q++) s[nt][q] *= SOFTMAX_SCALE;
        if (k0 == q0) {
            int r1 = q0 + wm * 16 + g, r2 = r1 + 8;
#pragma unroll
            for (int nt = 0; nt < 8; nt++) {
                int c0 = k0 + nt * 8 + t2;
                if (c0     > r1) s[nt][0] = -FLT_MAX;
                if (c0 + 1 > r1) s[nt][1] = -FLT_MAX;
                if (c0     > r2) s[nt][2] = -FLT_MAX;
                if (c0 + 1 > r2) s[nt][3] = -FLT_MAX;
            }
        }

        // ---- online softmax ----
        float tm1 = -FLT_MAX, tm2 = -FLT_MAX;
#pragma unroll
        for (int nt = 0; nt < 8; nt++) {
            tm1 = fmaxf(tm1, fmaxf(s[nt][0], s[nt][1]));
            tm2 = fmaxf(tm2, fmaxf(s[nt][2], s[nt][3]));
        }
        tm1 = fmaxf(tm1, __shfl_xor_sync(0xffffffffu, tm1, 1));
        tm1 = fmaxf(tm1, __shfl_xor_sync(0xffffffffu, tm1, 2));
        tm2 = fmaxf(tm2, __shfl_xor_sync(0xffffffffu, tm2, 1));
        tm2 = fmaxf(tm2, __shfl_xor_sync(0xffffffffu, tm2, 2));
        float nm1 = fmaxf(m1, tm1), nm2 = fmaxf(m2, tm2);
        float a1 = __expf(m1 - nm1), a2 = __expf(m2 - nm2);
        m1 = nm1; m2 = nm2;

        float rs1 = 0.f, rs2 = 0.f;
#pragma unroll
        for (int nt = 0; nt < 8; nt++) {
            s[nt][0] = __expf(s[nt][0] - nm1);
            s[nt][1] = __expf(s[nt][1] - nm1);
            s[nt][2] = __expf(s[nt][2] - nm2);
            s[nt][3] = __expf(s[nt][3] - nm2);
            rs1 += s[nt][0] + s[nt][1];
            rs2 += s[nt][2] + s[nt][3];
        }
        rs1 += __shfl_xor_sync(0xffffffffu, rs1, 1);
        rs1 += __shfl_xor_sync(0xffffffffu, rs1, 2);
        rs2 += __shfl_xor_sync(0xffffffffu, rs2, 1);
        rs2 += __shfl_xor_sync(0xffffffffu, rs2, 2);
        l1 = l1 * a1 + rs1;
        l2 = l2 * a2 + rs2;
#pragma unroll
        for (int nt = 0; nt < 16; nt++) {
            o[nt][0] *= a1; o[nt][1] *= a1;
            o[nt][2] *= a2; o[nt][3] *= a2;
        }

        // ---- P -> bf16 hi/lo fragments ----
        uint32_t hp01[8], hp23[8], lp01[8], lp23[8];
#pragma unroll
        for (int nt = 0; nt < 8; nt++) {
            split2(s[nt][0], s[nt][1], hp01[nt], lp01[nt]);
            split2(s[nt][2], s[nt][3], hp23[nt], lp23[nt]);
        }

        cp_wait<0>();       // V ready
        __syncthreads();    // all warps done reading K smem
        if (k0 + 64 <= q0) {   // prefetch next K during PV
#pragma unroll
            for (int i = 0; i < 16; i++) {
                int item = i * 128 + tid;
                int mat = item >> 10;
                int within = item & 1023;
                int kcg = within >> 6;
                int row = within & 63;
                const __nv_bfloat16* src = (mat ? pl : ph) + rowbase +
                                           (size_t)(k0 + 64 + row) * H3 + HID + kcg * 8;
                cp_async16((mat ? sKL : sKH) + kcg * 1024 + row * 16, src);
            }
            cp_commit();
        }

        // ---- O += P V ----
#pragma unroll
        for (int kt = 0; kt < 4; kt++) {
            uint32_t ah4[4] = {hp01[2*kt], hp23[2*kt], hp01[2*kt+1], hp23[2*kt+1]};
            uint32_t al4[4] = {lp01[2*kt], lp23[2*kt], lp01[2*kt+1], lp23[2*kt+1]};
#pragma unroll
            for (int np = 0; np < 8; np++) {
                uint32_t roff = (uint32_t)((np * 2 + (lane >> 4)) * 1024 +
                                           (kt * 16 + ((lane >> 3) & 1) * 8 + (lane & 7)) * 16);
                uint32_t vh4[4], vl4[4];
                ldsm_x4_t(vh4, sVH + roff);
                ldsm_x4_t(vl4, sVL + roff);
#pragma unroll
                for (int sub = 0; sub < 2; sub++) {
                    int nt = np * 2 + sub;
                    mma16816(o[nt], ah4, &vh4[sub * 2]);
                    mma16816(o[nt], ah4, &vl4[sub * 2]);
                    mma16816(o[nt], al4, &vh4[sub * 2]);
                }
            }
        }
        __syncthreads();    // PV readers done before next-iter V overwrite
    }

    // ---- finalize: write ctx as bf16 hi/lo ----
    float inv1 = 1.f / l1, inv2 = 1.f / l2;
    int r1 = q0 + wm * 16 + g;
    size_t base1 = (size_t)(b * SLEN + r1) * HID + h * HDIM;
    size_t base2 = base1 + 8 * HID;
#pragma unroll
    for (int nt = 0; nt < 16; nt++) {
        int col = nt * 8 + t2;
        uint32_t h0, l0, h1, l1w;
        split2(o[nt][0] * inv1, o[nt][1] * inv1, h0, l0);
        split2(o[nt][2] * inv2, o[nt][3] * inv2, h1, l1w);
        *(uint32_t*)(ch + base1 + col) = h0;
        *(uint32_t*)(cl + base1 + col) = l0;
        *(uint32_t*)(ch + base2 + col) = h1;
        *(uint32_t*)(cl + base2 + col) = l1w;
    }
}

// ============================ host entry =====================================
extern "C" void kernel_launch(void* const* d_in, const int* in_sizes, int n_in,
                              void* d_out, int out_size)
{
    const float* hidden = (const float*)d_in[0];
    const float* w_pack = (const float*)d_in[2];
    const float* w_o    = (const float*)d_in[3];
    float* out = (float*)d_out;

    __nv_bfloat16 *ph, *pl, *ch, *cl, *ah, *al, *bh, *bl;
    cudaGetSymbolAddress((void**)&ph, g_ph);
    cudaGetSymbolAddress((void**)&pl, g_pl);
    cudaGetSymbolAddress((void**)&ch, g_ch);
    cudaGetSymbolAddress((void**)&cl, g_cl);
    cudaGetSymbolAddress((void**)&ah, g_ah);
    cudaGetSymbolAddress((void**)&al, g_al);
    cudaGetSymbolAddress((void**)&bh, g_bh);
    cudaGetSymbolAddress((void**)&bl, g_bl);

    static bool attr_set = false;
    if (!attr_set) {
        cudaFuncSetAttribute(gemm_bf16s<0>, cudaFuncAttributeMaxDynamicSharedMemorySize, GT_SMEM);
        cudaFuncSetAttribute(gemm_bf16s<1>, cudaFuncAttributeMaxDynamicSharedMemorySize, GT_SMEM);
        cudaFuncSetAttribute(flash_tc,      cudaFuncAttributeMaxDynamicSharedMemorySize, FA_SMEM);
        attr_set = true;
    }

    // 1) split QKV inputs
    split_kernel<<<MROWS * HID / 4 / 256, 256>>>(hidden, ah, al, MROWS * HID);
    split_kernel<<<H3 * HID / 4 / 256, 256>>>(w_pack, bh, bl, H3 * HID);

    // 2) QKV projection -> bf16 hi/lo proj
    gemm_bf16s<1><<<dim3(H3 / GBN, MROWS / GBM), 256, GT_SMEM>>>(
        ah, al, bh, bl, nullptr, ph, pl, H3, HID);

    // 3) causal flash attention -> bf16 hi/lo ctx
    flash_tc<<<dim3(SLEN / 64, NHEADS, BATCH), 128, FA_SMEM>>>(ph, pl, ch, cl);

    // 4) split w_o, output projection -> fp32 out
    split_kernel<<<HID * HID / 4 / 256, 256>>>(w_o, bh, bl, HID * HID);
    gemm_bf16s<0><<<dim3(HID / GBN, MROWS / GBM), 256, GT_SMEM>>>(
        ch, cl, bh, bl, out, nullptr, nullptr, HID, HID);
}